// round 2
// baseline (speedup 1.0000x reference)
#include <cuda_runtime.h>
#include <cuda_bf16.h>

#define N_NODES_MAX 100000
#define N_EDGES_MAX 1600000
#define D_FEAT 64
#define D4 (D_FEAT / 4)   // 16 float4 per row

// ---- scratch (allocation-free device globals) ------------------------------
__device__ float g_xbuf0[N_NODES_MAX * D_FEAT];
__device__ float g_xbuf1[N_NODES_MAX * D_FEAT];
__device__ int   g_srcs[N_EDGES_MAX];           // CSR: src ids grouped by dst
__device__ int   g_rowstart[N_NODES_MAX + 1];
__device__ int   g_degi[N_NODES_MAX];
__device__ int   g_cursor[N_NODES_MAX];
__device__ float g_dinv[N_NODES_MAX];

// ---- CSR build --------------------------------------------------------------
__global__ void k_zero_deg(int n) {
    int i = blockIdx.x * blockDim.x + threadIdx.x;
    if (i < n) g_degi[i] = 0;
}

__global__ void k_count_deg(const int* __restrict__ dst, int ne) {
    int e = blockIdx.x * blockDim.x + threadIdx.x;
    if (e < ne) atomicAdd(&g_degi[dst[e]], 1);
}

// dinv from degree; also reset cursors
__global__ void k_dinv(int n) {
    int i = blockIdx.x * blockDim.x + threadIdx.x;
    if (i < n) {
        g_dinv[i]   = rsqrtf(fmaxf((float)g_degi[i], 1.0f));
        g_cursor[i] = 0;
    }
}

// single-block exclusive scan over g_degi -> g_rowstart (n up to 100k)
__global__ void k_scan(int n) {
    __shared__ int sums[1024];
    int tid   = threadIdx.x;
    int chunk = (n + 1023) / 1024;
    int begin = tid * chunk;
    int end   = begin + chunk; if (end > n) end = n;

    int s = 0;
    for (int i = begin; i < end; i++) s += g_degi[i];
    sums[tid] = s;
    __syncthreads();

    // Hillis–Steele inclusive scan over 1024 partial sums
    for (int off = 1; off < 1024; off <<= 1) {
        int v = (tid >= off) ? sums[tid - off] : 0;
        __syncthreads();
        sums[tid] += v;
        __syncthreads();
    }

    int run = (tid > 0) ? sums[tid - 1] : 0;   // exclusive prefix of my chunk
    for (int i = begin; i < end; i++) {
        g_rowstart[i] = run;
        run += g_degi[i];
    }
    if (tid == 1023) g_rowstart[n] = sums[1023];
}

__global__ void k_fill(const int* __restrict__ src,
                       const int* __restrict__ dst, int ne) {
    int e = blockIdx.x * blockDim.x + threadIdx.x;
    if (e >= ne) return;
    int d   = dst[e];
    int pos = g_rowstart[d] + atomicAdd(&g_cursor[d], 1);
    g_srcs[pos] = src[e];
}

// ---- fused propagation round -------------------------------------------------
// 16 threads per node d (q = float4 column). Computes
//   acc  = sum_{e in(d)} x_in[src[e]] * dinv[src[e]]
//   x_out[d] = x_in[d] - dinv[d] * acc
//   h[d]    += theta_k * x_out[d]         (or θ0*x_in + θ1*x_out when first)
__global__ void k_round(const float4* __restrict__ x_in,
                        float4* __restrict__ x_out,
                        float* __restrict__ h,
                        const float* __restrict__ theta,
                        int k, int first, int n) {
    int gid = blockIdx.x * blockDim.x + threadIdx.x;
    int d = gid >> 4;
    int q = gid & 15;
    if (d >= n) return;

    int rs = g_rowstart[d];
    int re = g_rowstart[d + 1];

    float4 acc = make_float4(0.f, 0.f, 0.f, 0.f);

    int e = rs;
    // fast path: batches of 16 edges, indices loaded coalesced then broadcast
    while (e + 16 <= re) {
        int   s_my  = g_srcs[e + q];
        float di_my = g_dinv[s_my];
#pragma unroll
        for (int j = 0; j < 16; j++) {
            int   s  = __shfl_sync(0xFFFFFFFFu, s_my, j, 16);
            float di = __shfl_sync(0xFFFFFFFFu, di_my, j, 16);
            float4 v = x_in[s * D4 + q];
            acc.x += v.x * di;
            acc.y += v.y * di;
            acc.z += v.z * di;
            acc.w += v.w * di;
        }
        e += 16;
    }
    // tail
    int cnt = re - e;
    if (cnt > 0) {
        int   s_my  = (q < cnt) ? g_srcs[e + q] : 0;
        float di_my = (q < cnt) ? g_dinv[s_my] : 0.f;
        for (int j = 0; j < cnt; j++) {
            int   s  = __shfl_sync(0xFFFFFFFFu, s_my, j, 16);
            float di = __shfl_sync(0xFFFFFFFFu, di_my, j, 16);
            float4 v = x_in[s * D4 + q];
            acc.x += v.x * di;
            acc.y += v.y * di;
            acc.z += v.z * di;
            acc.w += v.w * di;
        }
    }

    float dd  = g_dinv[d];
    float4 xa = x_in[d * D4 + q];
    float4 xn = make_float4(xa.x - acc.x * dd,
                            xa.y - acc.y * dd,
                            xa.z - acc.z * dd,
                            xa.w - acc.w * dd);
    x_out[d * D4 + q] = xn;

    float th = __ldg(&theta[k]);
    float4* h4 = reinterpret_cast<float4*>(h);
    float4 hh;
    if (first) {
        float t0 = __ldg(&theta[0]);
        hh = make_float4(t0 * xa.x + th * xn.x,
                         t0 * xa.y + th * xn.y,
                         t0 * xa.z + th * xn.z,
                         t0 * xa.w + th * xn.w);
    } else {
        hh = h4[d * D4 + q];
        hh.x += th * xn.x;
        hh.y += th * xn.y;
        hh.z += th * xn.z;
        hh.w += th * xn.w;
    }
    h4[d * D4 + q] = hh;
}

// ---------------------------------------------------------------------------
extern "C" void kernel_launch(void* const* d_in, const int* in_sizes, int n_in,
                              void* d_out, int out_size) {
    const float* feat  = (const float*)d_in[0];
    const float* theta = (const float*)d_in[1];
    const int*   src   = (const int*)d_in[2];
    const int*   dst   = (const int*)d_in[3];
    float* h = (float*)d_out;

    const int n  = in_sizes[0] / D_FEAT;
    const int K  = in_sizes[1];
    const int ne = in_sizes[2];

    const int T = 256;

    // CSR build
    k_zero_deg<<<(n + T - 1) / T, T>>>(n);
    k_count_deg<<<(ne + T - 1) / T, T>>>(dst, ne);
    k_dinv<<<(n + T - 1) / T, T>>>(n);
    k_scan<<<1, 1024>>>(n);
    k_fill<<<(ne + T - 1) / T, T>>>(src, dst, ne);

    // fused rounds, double-buffered x
    int gthreads = n * 16;
    int gblocks  = (gthreads + T - 1) / T;

    const float4* x_in = reinterpret_cast<const float4*>(feat);
    float4* bufs[2] = { reinterpret_cast<float4*>(g_xbuf0),
                        reinterpret_cast<float4*>(g_xbuf1) };
    // NOTE: device-global addresses can't be taken on host directly; use symbol trick below.
    // (handled via separate launch wrapper)
    (void)bufs;

    float4* xb0; float4* xb1;
    cudaGetSymbolAddress((void**)&xb0, g_xbuf0);
    cudaGetSymbolAddress((void**)&xb1, g_xbuf1);

    float4* x_out = xb0;
    for (int k = 1; k < K; k++) {
        k_round<<<gblocks, T>>>(x_in, x_out, h, theta, k, (k == 1) ? 1 : 0, n);
        x_in  = x_out;
        x_out = (x_out == xb0) ? xb1 : xb0;
    }
}

// round 3
// speedup vs baseline: 1.6185x; 1.6185x over previous
#include <cuda_runtime.h>
#include <cuda_bf16.h>

#define N_NODES_MAX 100000
#define N_EDGES_MAX 1600000
#define D_FEAT 64
#define D4 (D_FEAT / 4)       // 16 float4 per row
#define SCAN_BLK 1024         // elements (and threads) per scan block
#define MAX_SCAN_BLOCKS 128

// ---- scratch (allocation-free device globals) ------------------------------
__device__ float  g_ybuf0[N_NODES_MAX * D_FEAT];   // y = x * dinv (double buffer)
__device__ float  g_ybuf1[N_NODES_MAX * D_FEAT];
__device__ int    g_srcs[N_EDGES_MAX];             // CSR: src ids grouped by dst
__device__ int    g_rowstart[N_NODES_MAX + 1];
__device__ int    g_degi[N_NODES_MAX];
__device__ int    g_incl[N_NODES_MAX];             // per-block inclusive scans
__device__ int    g_bsum[MAX_SCAN_BLOCKS];
__device__ int    g_boff[MAX_SCAN_BLOCKS];
__device__ int    g_total;
__device__ int    g_cursor[N_NODES_MAX];
__device__ float2 g_dfac[N_NODES_MAX];             // (dinv^2, sqrt(max(deg,1)))
__device__ float  g_dinv[N_NODES_MAX];

// ---- CSR build --------------------------------------------------------------
__global__ void k_zero_deg(int n) {
    int i = blockIdx.x * blockDim.x + threadIdx.x;
    if (i < n) g_degi[i] = 0;
}

__global__ void k_count_deg(const int* __restrict__ dst, int ne) {
    int e = blockIdx.x * blockDim.x + threadIdx.x;
    if (e < ne) atomicAdd(&g_degi[dst[e]], 1);
}

__global__ void k_dfac(int n) {
    int i = blockIdx.x * blockDim.x + threadIdx.x;
    if (i < n) {
        float dg = fmaxf((float)g_degi[i], 1.0f);
        g_dinv[i]   = rsqrtf(dg);
        g_dfac[i]   = make_float2(1.0f / dg, sqrtf(dg));
        g_cursor[i] = 0;
    }
}

// --- parallel scan: stage 1, per-block inclusive scan (1024 elems/block) -----
__global__ void k_scan1(int n) {
    __shared__ int sh[SCAN_BLK];
    int tid = threadIdx.x;
    int i   = blockIdx.x * SCAN_BLK + tid;
    int v   = (i < n) ? g_degi[i] : 0;
    sh[tid] = v;
    __syncthreads();
#pragma unroll
    for (int off = 1; off < SCAN_BLK; off <<= 1) {
        int t = (tid >= off) ? sh[tid - off] : 0;
        __syncthreads();
        sh[tid] += t;
        __syncthreads();
    }
    if (i < n) g_incl[i] = sh[tid];
    if (tid == SCAN_BLK - 1) g_bsum[blockIdx.x] = sh[tid];
}

// --- stage 2: exclusive scan of block sums (1 block) --------------------------
__global__ void k_scan2(int nb) {
    __shared__ int sh[MAX_SCAN_BLOCKS];
    int tid = threadIdx.x;
    int v = (tid < nb) ? g_bsum[tid] : 0;
    sh[tid] = v;
    __syncthreads();
#pragma unroll
    for (int off = 1; off < MAX_SCAN_BLOCKS; off <<= 1) {
        int t = (tid >= off) ? sh[tid - off] : 0;
        __syncthreads();
        sh[tid] += t;
        __syncthreads();
    }
    if (tid < nb) g_boff[tid] = sh[tid] - v;   // exclusive
    if (tid == MAX_SCAN_BLOCKS - 1) g_total = sh[tid];
}

// --- stage 3: combine -> exclusive rowstart ------------------------------------
__global__ void k_scan3(int n) {
    int i = blockIdx.x * SCAN_BLK + threadIdx.x;
    if (i < n)
        g_rowstart[i] = g_incl[i] - g_degi[i] + g_boff[blockIdx.x];
    if (i == 0)
        g_rowstart[n] = g_total;
}

__global__ void k_fill(const int* __restrict__ src,
                       const int* __restrict__ dst, int ne) {
    int e = blockIdx.x * blockDim.x + threadIdx.x;
    if (e >= ne) return;
    int d   = dst[e];
    int pos = g_rowstart[d] + atomicAdd(&g_cursor[d], 1);
    g_srcs[pos] = src[e];
}

// y0 = feat * dinv   (one thread per float4)
__global__ void k_inity(const float4* __restrict__ feat, float4* __restrict__ y0, int n4) {
    int t = blockIdx.x * blockDim.x + threadIdx.x;
    if (t >= n4) return;
    float di = g_dinv[t >> 4];
    float4 f = feat[t];
    y0[t] = make_float4(f.x * di, f.y * di, f.z * di, f.w * di);
}

// ---- fused propagation round (in y-space) ------------------------------------
// 16 threads per node d (q = float4 column).
//   acc      = sum_{e in(d)} y_in[src[e]]
//   y_out[d] = y_in[d] - dinv2[d] * acc
//   x_k[d]   = y_out[d] * sqrtdeg[d]
//   h[d]    += theta_k * x_k[d]           (first round: h = th0*feat + th1*x_1)
__global__ void __launch_bounds__(256)
k_round(const float4* __restrict__ y_in,
        float4* __restrict__ y_out,
        const float4* __restrict__ feat,
        float* __restrict__ h,
        const float* __restrict__ theta,
        int k, int first, int n) {
    int gid = blockIdx.x * blockDim.x + threadIdx.x;
    int d = gid >> 4;
    int q = gid & 15;
    if (d >= n) return;

    int rs = g_rowstart[d];
    int re = g_rowstart[d + 1];

    float4 acc = make_float4(0.f, 0.f, 0.f, 0.f);

    int e = rs;
    while (e + 16 <= re) {
        int s_my = g_srcs[e + q];
#pragma unroll
        for (int j = 0; j < 16; j++) {
            int s = __shfl_sync(0xFFFFFFFFu, s_my, j, 16);
            float4 v = y_in[s * D4 + q];
            acc.x += v.x; acc.y += v.y; acc.z += v.z; acc.w += v.w;
        }
        e += 16;
    }
    int cnt = re - e;
    if (cnt > 0) {
        int s_my = (q < cnt) ? g_srcs[e + q] : 0;
        for (int j = 0; j < cnt; j++) {
            int s = __shfl_sync(0xFFFFFFFFu, s_my, j, 16);
            float4 v = y_in[s * D4 + q];
            acc.x += v.x; acc.y += v.y; acc.z += v.z; acc.w += v.w;
        }
    }

    float2 dc = g_dfac[d];          // (dinv^2, sqrt(deg))
    float4 yi = y_in[d * D4 + q];
    float4 yo = make_float4(yi.x - dc.x * acc.x,
                            yi.y - dc.x * acc.y,
                            yi.z - dc.x * acc.z,
                            yi.w - dc.x * acc.w);
    y_out[d * D4 + q] = yo;

    float th = __ldg(&theta[k]);
    float ts = th * dc.y;           // theta_k * sqrt(deg): h += ts * y_out
    float4* h4 = reinterpret_cast<float4*>(h);
    float4 hh;
    if (first) {
        float t0 = __ldg(&theta[0]);
        float4 f = feat[d * D4 + q];
        hh = make_float4(t0 * f.x + ts * yo.x,
                         t0 * f.y + ts * yo.y,
                         t0 * f.z + ts * yo.z,
                         t0 * f.w + ts * yo.w);
    } else {
        hh = h4[d * D4 + q];
        hh.x += ts * yo.x;
        hh.y += ts * yo.y;
        hh.z += ts * yo.z;
        hh.w += ts * yo.w;
    }
    h4[d * D4 + q] = hh;
}

// ---------------------------------------------------------------------------
extern "C" void kernel_launch(void* const* d_in, const int* in_sizes, int n_in,
                              void* d_out, int out_size) {
    const float* feat  = (const float*)d_in[0];
    const float* theta = (const float*)d_in[1];
    const int*   src   = (const int*)d_in[2];
    const int*   dst   = (const int*)d_in[3];
    float* h = (float*)d_out;

    const int n  = in_sizes[0] / D_FEAT;
    const int K  = in_sizes[1];
    const int ne = in_sizes[2];
    const int n4 = n * D4;

    const int T = 256;
    const int nb = (n + SCAN_BLK - 1) / SCAN_BLK;   // 98 for n=100k

    // CSR build
    k_zero_deg<<<(n + T - 1) / T, T>>>(n);
    k_count_deg<<<(ne + T - 1) / T, T>>>(dst, ne);
    k_dfac<<<(n + T - 1) / T, T>>>(n);
    k_scan1<<<nb, SCAN_BLK>>>(n);
    k_scan2<<<1, MAX_SCAN_BLOCKS>>>(nb);
    k_scan3<<<nb, SCAN_BLK>>>(n);
    k_fill<<<(ne + T - 1) / T, T>>>(src, dst, ne);

    float4* yb0; float4* yb1;
    cudaGetSymbolAddress((void**)&yb0, g_ybuf0);
    cudaGetSymbolAddress((void**)&yb1, g_ybuf1);

    k_inity<<<(n4 + T - 1) / T, T>>>(reinterpret_cast<const float4*>(feat), yb0, n4);

    int gthreads = n * 16;
    int gblocks  = (gthreads + T - 1) / T;

    const float4* y_in = yb0;
    float4* y_out = yb1;
    for (int k = 1; k < K; k++) {
        k_round<<<gblocks, T>>>(y_in, y_out,
                                reinterpret_cast<const float4*>(feat),
                                h, theta, k, (k == 1) ? 1 : 0, n);
        const float4* t = y_out;
        y_out = (float4*)y_in;
        y_in  = t;
    }
}

// round 4
// speedup vs baseline: 1.6410x; 1.0139x over previous
#include <cuda_runtime.h>
#include <cuda_bf16.h>

#define N_NODES_MAX 100000
#define N_EDGES_MAX 1600000
#define D_FEAT 64
#define D4 (D_FEAT / 4)       // 16 float4 per row
#define SCAN_BLK 1024
#define MAX_SCAN_BLOCKS 128
#define K_MAX 5

// ---- scratch (allocation-free device globals) ------------------------------
__device__ float  g_y[K_MAX][N_NODES_MAX * D_FEAT];  // y_0..y_4 (y = x * dinv)
__device__ int    g_srcs[N_EDGES_MAX];               // CSR: src ids grouped by dst
__device__ int    g_rowstart[N_NODES_MAX + 1];
__device__ int    g_degi[N_NODES_MAX];
__device__ int    g_incl[N_NODES_MAX];
__device__ int    g_bsum[MAX_SCAN_BLOCKS];
__device__ int    g_boff[MAX_SCAN_BLOCKS];
__device__ int    g_total;
__device__ int    g_cursor[N_NODES_MAX];
__device__ float2 g_dfac[N_NODES_MAX];               // (1/deg, sqrt(deg))
__device__ float  g_dinv[N_NODES_MAX];

// ---- CSR build --------------------------------------------------------------
__global__ void k_zero_deg(int n) {
    int i = blockIdx.x * blockDim.x + threadIdx.x;
    if (i < n) g_degi[i] = 0;
}

__global__ void k_count_deg(const int* __restrict__ dst, int ne) {
    int e = blockIdx.x * blockDim.x + threadIdx.x;
    if (e < ne) atomicAdd(&g_degi[dst[e]], 1);
}

// fused: per-node factors + per-block inclusive scan of degrees
__global__ void k_dfac_scan1(int n) {
    __shared__ int sh[SCAN_BLK];
    int tid = threadIdx.x;
    int i   = blockIdx.x * SCAN_BLK + tid;
    int deg = (i < n) ? g_degi[i] : 0;
    if (i < n) {
        float dg  = fmaxf((float)deg, 1.0f);
        g_dinv[i]   = rsqrtf(dg);
        g_dfac[i]   = make_float2(1.0f / dg, sqrtf(dg));
        g_cursor[i] = 0;
    }
    sh[tid] = deg;
    __syncthreads();
#pragma unroll
    for (int off = 1; off < SCAN_BLK; off <<= 1) {
        int t = (tid >= off) ? sh[tid - off] : 0;
        __syncthreads();
        sh[tid] += t;
        __syncthreads();
    }
    if (i < n) g_incl[i] = sh[tid];
    if (tid == SCAN_BLK - 1) g_bsum[blockIdx.x] = sh[tid];
}

__global__ void k_scan2(int nb) {
    __shared__ int sh[MAX_SCAN_BLOCKS];
    int tid = threadIdx.x;
    int v = (tid < nb) ? g_bsum[tid] : 0;
    sh[tid] = v;
    __syncthreads();
#pragma unroll
    for (int off = 1; off < MAX_SCAN_BLOCKS; off <<= 1) {
        int t = (tid >= off) ? sh[tid - off] : 0;
        __syncthreads();
        sh[tid] += t;
        __syncthreads();
    }
    if (tid < nb) g_boff[tid] = sh[tid] - v;
    if (tid == MAX_SCAN_BLOCKS - 1) g_total = sh[tid];
}

__global__ void k_scan3(int n) {
    int i = blockIdx.x * SCAN_BLK + threadIdx.x;
    if (i < n)
        g_rowstart[i] = g_incl[i] - g_degi[i] + g_boff[blockIdx.x];
    if (i == 0)
        g_rowstart[n] = g_total;
}

__global__ void k_fill(const int* __restrict__ src,
                       const int* __restrict__ dst, int ne) {
    int e = blockIdx.x * blockDim.x + threadIdx.x;
    if (e >= ne) return;
    int d   = dst[e];
    int pos = g_rowstart[d] + atomicAdd(&g_cursor[d], 1);
    g_srcs[pos] = src[e];
}

// y0 = feat * dinv
__global__ void k_inity(const float4* __restrict__ feat, float4* __restrict__ y0, int n4) {
    int t = blockIdx.x * blockDim.x + threadIdx.x;
    if (t >= n4) return;
    float di = g_dinv[t >> 4];
    float4 f = feat[t];
    y0[t] = make_float4(f.x * di, f.y * di, f.z * di, f.w * di);
}

// ---- fused propagation round (y-space, packed f32x2 accumulation) ------------
// 16 threads per node d (q = float4 column):
//   acc      = sum_{e in(d)} y_in[src[e]]
//   y_out[d] = y_in[d] - (1/deg[d]) * acc
__global__ void __launch_bounds__(256)
k_round(const float* __restrict__ y_in,
        float* __restrict__ y_out,
        int n) {
    int gid = blockIdx.x * blockDim.x + threadIdx.x;
    int d = gid >> 4;
    int q = gid & 15;
    if (d >= n) return;

    int rs = g_rowstart[d];
    int re = g_rowstart[d + 1];

    // per-lane base: row byte offset q*16
    const char* base = reinterpret_cast<const char*>(y_in) + q * 16;

    unsigned long long a0 = 0ull, a1 = 0ull;   // packed f32x2 accumulators

    int e = rs;
    while (e + 16 <= re) {
        int off_my = g_srcs[e + q] << 8;       // src row byte offset (64 floats * 4B)
#pragma unroll
        for (int j = 0; j < 16; j++) {
            int off = __shfl_sync(0xFFFFFFFFu, off_my, j, 16);
            ulonglong2 v = *reinterpret_cast<const ulonglong2*>(base + off);
            asm("add.rn.f32x2 %0, %0, %1;" : "+l"(a0) : "l"(v.x));
            asm("add.rn.f32x2 %0, %0, %1;" : "+l"(a1) : "l"(v.y));
        }
        e += 16;
    }
    int cnt = re - e;
    if (cnt > 0) {
        int off_my = (q < cnt) ? (g_srcs[e + q] << 8) : 0;
        for (int j = 0; j < cnt; j++) {
            int off = __shfl_sync(0xFFFFFFFFu, off_my, j, 16);
            ulonglong2 v = *reinterpret_cast<const ulonglong2*>(base + off);
            asm("add.rn.f32x2 %0, %0, %1;" : "+l"(a0) : "l"(v.x));
            asm("add.rn.f32x2 %0, %0, %1;" : "+l"(a1) : "l"(v.y));
        }
    }

    float4 acc;
    acc.x = __uint_as_float((unsigned)(a0 & 0xFFFFFFFFull));
    acc.y = __uint_as_float((unsigned)(a0 >> 32));
    acc.z = __uint_as_float((unsigned)(a1 & 0xFFFFFFFFull));
    acc.w = __uint_as_float((unsigned)(a1 >> 32));

    float invdeg = g_dfac[d].x;
    int t = d * D4 + q;
    float4 yi = reinterpret_cast<const float4*>(y_in)[t];
    float4 yo = make_float4(yi.x - invdeg * acc.x,
                            yi.y - invdeg * acc.y,
                            yi.z - invdeg * acc.z,
                            yi.w - invdeg * acc.w);
    reinterpret_cast<float4*>(y_out)[t] = yo;
}

// ---- final combine: h = th0*feat + sum_k thk * sqrt(deg) * y_k ----------------
__global__ void k_final(const float4* __restrict__ feat,
                        float* __restrict__ h,
                        const float* __restrict__ theta,
                        int K, int n4) {
    int t = blockIdx.x * blockDim.x + threadIdx.x;
    if (t >= n4) return;
    int node = t >> 4;
    float sd = g_dfac[node].y;
    float4 f = feat[t];
    float t0 = __ldg(&theta[0]);
    float4 hh = make_float4(t0 * f.x, t0 * f.y, t0 * f.z, t0 * f.w);
#pragma unroll
    for (int k = 1; k < K_MAX; k++) {
        if (k >= K) break;
        float ts = __ldg(&theta[k]) * sd;
        float4 y = reinterpret_cast<const float4*>(g_y[k])[t];
        hh.x += ts * y.x;
        hh.y += ts * y.y;
        hh.z += ts * y.z;
        hh.w += ts * y.w;
    }
    reinterpret_cast<float4*>(h)[t] = hh;
}

// ---------------------------------------------------------------------------
extern "C" void kernel_launch(void* const* d_in, const int* in_sizes, int n_in,
                              void* d_out, int out_size) {
    const float* feat  = (const float*)d_in[0];
    const float* theta = (const float*)d_in[1];
    const int*   src   = (const int*)d_in[2];
    const int*   dst   = (const int*)d_in[3];
    float* h = (float*)d_out;

    const int n  = in_sizes[0] / D_FEAT;
    const int K  = in_sizes[1];
    const int ne = in_sizes[2];
    const int n4 = n * D4;

    const int T  = 256;
    const int nb = (n + SCAN_BLK - 1) / SCAN_BLK;

    // CSR build
    k_zero_deg<<<(n + T - 1) / T, T>>>(n);
    k_count_deg<<<(ne + T - 1) / T, T>>>(dst, ne);
    k_dfac_scan1<<<nb, SCAN_BLK>>>(n);
    k_scan2<<<1, MAX_SCAN_BLOCKS>>>(nb);
    k_scan3<<<nb, SCAN_BLK>>>(n);
    k_fill<<<(ne + T - 1) / T, T>>>(src, dst, ne);

    float* ybase;
    cudaGetSymbolAddress((void**)&ybase, g_y);
    const size_t ystride = (size_t)N_NODES_MAX * D_FEAT;

    k_inity<<<(n4 + T - 1) / T, T>>>(reinterpret_cast<const float4*>(feat),
                                     reinterpret_cast<float4*>(ybase), n4);

    int gthreads = n * 16;
    int gblocks  = (gthreads + T - 1) / T;

    for (int k = 1; k < K; k++) {
        k_round<<<gblocks, T>>>(ybase + (size_t)(k - 1) * ystride,
                                ybase + (size_t)k * ystride, n);
    }

    k_final<<<(n4 + T - 1) / T, T>>>(reinterpret_cast<const float4*>(feat),
                                     h, theta, K, n4);
}

// round 5
// speedup vs baseline: 2.2803x; 1.3896x over previous
#include <cuda_runtime.h>
#include <cuda_bf16.h>

#define N_NODES_MAX 100000
#define N_EDGES_MAX 1600000
#define D_FEAT 64
#define D4 (D_FEAT / 4)
#define SCAN_BLK 1024
#define MAX_SCAN_BLOCKS 128
#define K_MAX 5

// ---- scratch (allocation-free device globals) ------------------------------
__device__ float  g_y[K_MAX][N_NODES_MAX * D_FEAT];  // y_0..y_4 (y = x * dinv)
__device__ int    g_srcs[N_EDGES_MAX];               // CSR: src ids grouped by dst
__device__ int    g_rowstart[N_NODES_MAX + 1];
__device__ int    g_degi[N_NODES_MAX];
__device__ int    g_incl[N_NODES_MAX];
__device__ int    g_bsum[MAX_SCAN_BLOCKS];
__device__ int    g_cursor[N_NODES_MAX];
__device__ float2 g_dfac[N_NODES_MAX];               // (1/deg, sqrt(deg))
__device__ float  g_dinv[N_NODES_MAX];

// ---- CSR build --------------------------------------------------------------
__global__ void k_count_deg(const int* __restrict__ dst, int ne) {
    int e = blockIdx.x * blockDim.x + threadIdx.x;
    if (e < ne) atomicAdd(&g_degi[dst[e]], 1);
}

// per-node factors + per-block inclusive scan of degrees
__global__ void k_dfac_scan1(int n) {
    __shared__ int sh[SCAN_BLK];
    int tid = threadIdx.x;
    int i   = blockIdx.x * SCAN_BLK + tid;
    int deg = (i < n) ? g_degi[i] : 0;
    if (i < n) {
        float dg    = fmaxf((float)deg, 1.0f);
        g_dinv[i]   = rsqrtf(dg);
        g_dfac[i]   = make_float2(1.0f / dg, sqrtf(dg));
        g_cursor[i] = 0;
    }
    sh[tid] = deg;
    __syncthreads();
#pragma unroll
    for (int off = 1; off < SCAN_BLK; off <<= 1) {
        int t = (tid >= off) ? sh[tid - off] : 0;
        __syncthreads();
        sh[tid] += t;
        __syncthreads();
    }
    if (i < n) g_incl[i] = sh[tid];
    if (tid == SCAN_BLK - 1) g_bsum[blockIdx.x] = sh[tid];
}

// merged scan2+scan3: every block redundantly warp-scans the <=128 block sums,
// then writes its slice of the exclusive rowstart.
__global__ void k_scan23(int n, int nb) {
    __shared__ int sh[MAX_SCAN_BLOCKS + 1];   // exclusive prefixes + total
    int tid = threadIdx.x;
    if (tid < 32) {
        int base = tid * 4;
        int v0 = (base + 0 < nb) ? g_bsum[base + 0] : 0;
        int v1 = (base + 1 < nb) ? g_bsum[base + 1] : 0;
        int v2 = (base + 2 < nb) ? g_bsum[base + 2] : 0;
        int v3 = (base + 3 < nb) ? g_bsum[base + 3] : 0;
        int s0 = v0, s1 = s0 + v1, s2 = s1 + v2, s3 = s2 + v3;
        int inc = s3;
#pragma unroll
        for (int off = 1; off < 32; off <<= 1) {
            int t = __shfl_up_sync(0xFFFFFFFFu, inc, off);
            if (tid >= off) inc += t;
        }
        int excl = inc - s3;
        sh[base + 0] = excl;
        sh[base + 1] = excl + s0;
        sh[base + 2] = excl + s1;
        sh[base + 3] = excl + s2;
        if (tid == 31) sh[MAX_SCAN_BLOCKS] = excl + s3;   // total
    }
    __syncthreads();
    int i = blockIdx.x * SCAN_BLK + tid;
    if (i < n)
        g_rowstart[i] = g_incl[i] - g_degi[i] + sh[blockIdx.x];
    if (i == 0)
        g_rowstart[n] = sh[MAX_SCAN_BLOCKS];
}

// fused: CSR fill (i < ne) + y0 = feat * dinv (i < n4)
__global__ void k_fill_init(const int* __restrict__ src,
                            const int* __restrict__ dst, int ne,
                            const float4* __restrict__ feat,
                            float4* __restrict__ y0, int n4) {
    int i = blockIdx.x * blockDim.x + threadIdx.x;
    if (i < ne) {
        int d   = dst[i];
        int pos = g_rowstart[d] + atomicAdd(&g_cursor[d], 1);
        g_srcs[pos] = src[i];
    }
    if (i < n4) {
        float di = g_dinv[i >> 4];
        float4 f = feat[i];
        y0[i] = make_float4(f.x * di, f.y * di, f.z * di, f.w * di);
    }
}

// ---- propagation round: ONE WARP PER NODE ------------------------------------
// lane owns floats [2*lane, 2*lane+1] of the 64-float row (8 bytes).
//   acc      = sum_{e in(d)} y_in[src[e]]
//   y_out[d] = y_in[d] - (1/deg[d]) * acc
__global__ void __launch_bounds__(256)
k_round(const float* __restrict__ y_in,
        float* __restrict__ y_out,
        int n) {
    int gid  = blockIdx.x * blockDim.x + threadIdx.x;
    int d    = gid >> 5;
    int lane = gid & 31;
    if (d >= n) return;

    int rs = g_rowstart[d];
    int re = g_rowstart[d + 1];

    const char* base = reinterpret_cast<const char*>(y_in) + lane * 8;
    unsigned long long a0 = 0ull;

    int e = rs;
    // fast path: 32-edge batches, coalesced index load + broadcast
    while (e + 32 <= re) {
        int off_my = g_srcs[e + lane] << 8;   // row byte offset (64 floats * 4B)
#pragma unroll
        for (int j = 0; j < 32; j++) {
            int off = __shfl_sync(0xFFFFFFFFu, off_my, j);
            unsigned long long v = *reinterpret_cast<const unsigned long long*>(base + off);
            asm("add.rn.f32x2 %0, %0, %1;" : "+l"(a0) : "l"(v));
        }
        e += 32;
    }
    // tail: up to 31 edges, unrolled x4 for MLP
    int cnt = re - e;
    if (cnt > 0) {
        int off_my = (lane < cnt) ? (g_srcs[e + lane] << 8) : 0;
        int j = 0;
        for (; j + 4 <= cnt; j += 4) {
            int o0 = __shfl_sync(0xFFFFFFFFu, off_my, j + 0);
            int o1 = __shfl_sync(0xFFFFFFFFu, off_my, j + 1);
            int o2 = __shfl_sync(0xFFFFFFFFu, off_my, j + 2);
            int o3 = __shfl_sync(0xFFFFFFFFu, off_my, j + 3);
            unsigned long long v0 = *reinterpret_cast<const unsigned long long*>(base + o0);
            unsigned long long v1 = *reinterpret_cast<const unsigned long long*>(base + o1);
            unsigned long long v2 = *reinterpret_cast<const unsigned long long*>(base + o2);
            unsigned long long v3 = *reinterpret_cast<const unsigned long long*>(base + o3);
            asm("add.rn.f32x2 %0, %0, %1;" : "+l"(a0) : "l"(v0));
            asm("add.rn.f32x2 %0, %0, %1;" : "+l"(a0) : "l"(v1));
            asm("add.rn.f32x2 %0, %0, %1;" : "+l"(a0) : "l"(v2));
            asm("add.rn.f32x2 %0, %0, %1;" : "+l"(a0) : "l"(v3));
        }
        for (; j < cnt; j++) {
            int off = __shfl_sync(0xFFFFFFFFu, off_my, j);
            unsigned long long v = *reinterpret_cast<const unsigned long long*>(base + off);
            asm("add.rn.f32x2 %0, %0, %1;" : "+l"(a0) : "l"(v));
        }
    }

    float2 acc;
    acc.x = __uint_as_float((unsigned)(a0 & 0xFFFFFFFFull));
    acc.y = __uint_as_float((unsigned)(a0 >> 32));

    float invdeg = g_dfac[d].x;
    int t = d * 32 + lane;   // float2 index
    float2 yi = reinterpret_cast<const float2*>(y_in)[t];
    float2 yo = make_float2(yi.x - invdeg * acc.x,
                            yi.y - invdeg * acc.y);
    reinterpret_cast<float2*>(y_out)[t] = yo;
}

// ---- final combine: h = th0*feat + sum_k thk * sqrt(deg) * y_k ----------------
__global__ void k_final(const float4* __restrict__ feat,
                        float* __restrict__ h,
                        const float* __restrict__ theta,
                        int K, int n4) {
    int t = blockIdx.x * blockDim.x + threadIdx.x;
    if (t >= n4) return;
    int node = t >> 4;
    float sd = g_dfac[node].y;
    float4 f = feat[t];
    float t0 = __ldg(&theta[0]);
    float4 hh = make_float4(t0 * f.x, t0 * f.y, t0 * f.z, t0 * f.w);
#pragma unroll
    for (int k = 1; k < K_MAX; k++) {
        if (k >= K) break;
        float ts = __ldg(&theta[k]) * sd;
        float4 y = reinterpret_cast<const float4*>(g_y[k])[t];
        hh.x += ts * y.x;
        hh.y += ts * y.y;
        hh.z += ts * y.z;
        hh.w += ts * y.w;
    }
    reinterpret_cast<float4*>(h)[t] = hh;
}

// ---------------------------------------------------------------------------
extern "C" void kernel_launch(void* const* d_in, const int* in_sizes, int n_in,
                              void* d_out, int out_size) {
    const float* feat  = (const float*)d_in[0];
    const float* theta = (const float*)d_in[1];
    const int*   src   = (const int*)d_in[2];
    const int*   dst   = (const int*)d_in[3];
    float* h = (float*)d_out;

    const int n  = in_sizes[0] / D_FEAT;
    const int K  = in_sizes[1];
    const int ne = in_sizes[2];
    const int n4 = n * D4;

    const int T  = 256;
    const int nb = (n + SCAN_BLK - 1) / SCAN_BLK;

    void* degi_addr;
    cudaGetSymbolAddress(&degi_addr, g_degi);
    float* ybase;
    cudaGetSymbolAddress((void**)&ybase, g_y);
    const size_t ystride = (size_t)N_NODES_MAX * D_FEAT;

    // CSR build
    cudaMemsetAsync(degi_addr, 0, (size_t)n * sizeof(int));
    k_count_deg<<<(ne + T - 1) / T, T>>>(dst, ne);
    k_dfac_scan1<<<nb, SCAN_BLK>>>(n);
    k_scan23<<<nb, SCAN_BLK>>>(n, nb);

    int mx = (ne > n4) ? ne : n4;
    k_fill_init<<<(mx + T - 1) / T, T>>>(src, dst, ne,
                                         reinterpret_cast<const float4*>(feat),
                                         reinterpret_cast<float4*>(ybase), n4);

    // propagation rounds (warp per node)
    int gthreads = n * 32;
    int gblocks  = (gthreads + T - 1) / T;
    for (int k = 1; k < K; k++) {
        k_round<<<gblocks, T>>>(ybase + (size_t)(k - 1) * ystride,
                                ybase + (size_t)k * ystride, n);
    }

    k_final<<<(n4 + T - 1) / T, T>>>(reinterpret_cast<const float4*>(feat),
                                     h, theta, K, n4);
}